// round 3
// baseline (speedup 1.0000x reference)
#include <cuda_runtime.h>
#include <math.h>

#define DIM   4096
#define NH    32
#define HD    128
#define SEQ   4096
#define BATCH 16

typedef unsigned long long u64;

// Scratch (allocation-free)
__device__ float g_q   [BATCH * DIM];
__device__ float g_kn  [BATCH * DIM];
__device__ float g_vn  [BATCH * DIM];
__device__ float g_attT[DIM * BATCH];   // transposed: [d_global][b]
__device__ float g_xT  [DIM * BATCH];   // transposed: [k][b]

// ---------------- packed fp32x2 helpers ----------------
__device__ __forceinline__ u64 ffma2(u64 a, u64 b, u64 c) {
    u64 d; asm("fma.rn.f32x2 %0, %1, %2, %3;" : "=l"(d) : "l"(a), "l"(b), "l"(c)); return d;
}
__device__ __forceinline__ u64 fadd2(u64 a, u64 b) {
    u64 d; asm("add.rn.f32x2 %0, %1, %2;" : "=l"(d) : "l"(a), "l"(b)); return d;
}
__device__ __forceinline__ u64 pack2(float lo, float hi) {
    u64 r; asm("mov.b64 %0, {%1, %2};" : "=l"(r) : "f"(lo), "f"(hi)); return r;
}
__device__ __forceinline__ void unpack2(u64 v, float& lo, float& hi) {
    asm("mov.b64 {%0, %1}, %2;" : "=f"(lo), "=f"(hi) : "l"(v));
}

// ---------------------------------------------------------------------------
// Transpose x: g_xT[k*16 + b] = x[b*4096 + k]
// ---------------------------------------------------------------------------
__global__ void transpose_x(const float* __restrict__ x) {
    int t = blockIdx.x * blockDim.x + threadIdx.x;   // 65536 threads
    int b = t >> 12;
    int k = t & (DIM - 1);
    g_xT[k * BATCH + b] = x[t];
}

// ---------------------------------------------------------------------------
// Skinny GEMM core: out[b][j] = sum_k W[j][k] * xT[k][b]
// One warp handles 4 consecutive W rows, all 16 batches, split-K over lanes.
// Accumulators: 4 rows x 8 batch-pairs in packed f32x2.
// ---------------------------------------------------------------------------
__device__ __forceinline__ void gemm_blk(const float* __restrict__ xT,
                                         const float* __restrict__ Wrows, // W + j0*DIM
                                         float* __restrict__ out,         // [b*DIM + j]
                                         int j0) {
    int lane = threadIdx.x & 31;

    u64 acc[4][8];
#pragma unroll
    for (int r = 0; r < 4; r++)
#pragma unroll
        for (int p = 0; p < 8; p++) acc[r][p] = 0ull;

    const float4* w4_0 = reinterpret_cast<const float4*>(Wrows + 0 * DIM);
    const float4* w4_1 = reinterpret_cast<const float4*>(Wrows + 1 * DIM);
    const float4* w4_2 = reinterpret_cast<const float4*>(Wrows + 2 * DIM);
    const float4* w4_3 = reinterpret_cast<const float4*>(Wrows + 3 * DIM);

    for (int kb = 0; kb < DIM / 128; kb++) {
        int fidx = kb * 32 + lane;        // float4 index into W rows
        float wv[4][4];
        *reinterpret_cast<float4*>(wv[0]) = __ldcs(w4_0 + fidx);
        *reinterpret_cast<float4*>(wv[1]) = __ldcs(w4_1 + fidx);
        *reinterpret_cast<float4*>(wv[2]) = __ldcs(w4_2 + fidx);
        *reinterpret_cast<float4*>(wv[3]) = __ldcs(w4_3 + fidx);

        int k0 = fidx * 4;
#pragma unroll
        for (int kk = 0; kk < 4; kk++) {
            const ulonglong2* xr =
                reinterpret_cast<const ulonglong2*>(xT + (size_t)(k0 + kk) * BATCH);
            ulonglong2 xa = xr[0], xb = xr[1], xc = xr[2], xd = xr[3];
            u64 xp[8] = {xa.x, xa.y, xb.x, xb.y, xc.x, xc.y, xd.x, xd.y};

            u64 wp0 = pack2(wv[0][kk], wv[0][kk]);
            u64 wp1 = pack2(wv[1][kk], wv[1][kk]);
            u64 wp2 = pack2(wv[2][kk], wv[2][kk]);
            u64 wp3 = pack2(wv[3][kk], wv[3][kk]);
#pragma unroll
            for (int p = 0; p < 8; p++) {
                acc[0][p] = ffma2(wp0, xp[p], acc[0][p]);
                acc[1][p] = ffma2(wp1, xp[p], acc[1][p]);
                acc[2][p] = ffma2(wp2, xp[p], acc[2][p]);
                acc[3][p] = ffma2(wp3, xp[p], acc[3][p]);
            }
        }
    }

    // split-K butterfly reduce (packed)
#pragma unroll
    for (int r = 0; r < 4; r++)
#pragma unroll
        for (int p = 0; p < 8; p++) {
#pragma unroll
            for (int off = 16; off; off >>= 1)
                acc[r][p] = fadd2(acc[r][p],
                                  __shfl_xor_sync(0xffffffffu, acc[r][p], off));
        }

    if (lane < 4) {
        int r = lane;
#pragma unroll
        for (int p = 0; p < 8; p++) {
            float lo, hi;
            unpack2(acc[r][p], lo, hi);
            out[(size_t)(2 * p + 0) * DIM + j0 + r] = lo;
            out[(size_t)(2 * p + 1) * DIM + j0 + r] = hi;
        }
    }
}

// QKV: 384 blocks x 256 threads; each block covers 32 consecutive rows of the
// fused [wq;wk;wv] row space (blocks never straddle a matrix boundary).
__global__ void __launch_bounds__(256) qkv_gemm(const float* __restrict__ wq,
                                                const float* __restrict__ wk,
                                                const float* __restrict__ wv) {
    int w  = threadIdx.x >> 5;
    int jg = blockIdx.x * 32 + w * 4;     // global fused row
    int which = jg >> 12;
    int jl    = jg & (DIM - 1);
    const float* W   = (which == 0) ? wq  : (which == 1) ? wk   : wv;
    float*       out = (which == 0) ? g_q : (which == 1) ? g_kn : g_vn;
    gemm_blk(g_xT, W + (size_t)jl * DIM, out, jl);
}

// O projection: 128 blocks x 256 threads, reads transposed attention output.
__global__ void __launch_bounds__(256) oproj_gemm(const float* __restrict__ wo,
                                                  float* __restrict__ out) {
    int w = threadIdx.x >> 5;
    int j = blockIdx.x * 32 + w * 4;
    gemm_blk(g_attT, wo + (size_t)j * DIM, out, j);
}

// ---------------------------------------------------------------------------
// Decode attention. One block per (b,h): 512 blocks, 8 warps. Each warp
// processes row pairs (r, r+8) stepping 16 (2-row unroll -> 2x MLP and
// interleaved shuffle chains). Streaming loads. Writes transposed output.
// ---------------------------------------------------------------------------
__global__ void __launch_bounds__(256) decode_attn(const float* __restrict__ kc,
                                                   const float* __restrict__ vc) {
    int bh   = blockIdx.x;
    int b    = bh >> 5;
    int h    = bh & 31;
    int tid  = threadIdx.x;
    int w    = tid >> 5;
    int lane = tid & 31;

    const float4* K = reinterpret_cast<const float4*>(kc + (size_t)bh * SEQ * HD);
    const float4* V = reinterpret_cast<const float4*>(vc + (size_t)bh * SEQ * HD);

    float4 q4 = reinterpret_cast<const float4*>(g_q + b * DIM + h * HD)[lane];
    const float scale = 0.08838834764831845f;   // 1/sqrt(128)

    float  m = -INFINITY;
    float  l = 0.f;
    float4 o = make_float4(0.f, 0.f, 0.f, 0.f);

    for (int i = 0; i < SEQ / 16; i++) {
        int r1 = i * 16 + w;
        int r2 = r1 + 8;
        float4 k1 = __ldcs(K + (size_t)r1 * (HD / 4) + lane);
        float4 v1 = __ldcs(V + (size_t)r1 * (HD / 4) + lane);
        float4 k2 = __ldcs(K + (size_t)r2 * (HD / 4) + lane);
        float4 v2 = __ldcs(V + (size_t)r2 * (HD / 4) + lane);

        float s1 = q4.x * k1.x + q4.y * k1.y + q4.z * k1.z + q4.w * k1.w;
        float s2 = q4.x * k2.x + q4.y * k2.y + q4.z * k2.z + q4.w * k2.w;
#pragma unroll
        for (int off = 16; off; off >>= 1) {
            s1 += __shfl_xor_sync(0xffffffffu, s1, off);
            s2 += __shfl_xor_sync(0xffffffffu, s2, off);
        }
        s1 *= scale;
        s2 *= scale;

        float nm = fmaxf(m, fmaxf(s1, s2));
        float c  = __expf(m - nm);
        float p1 = __expf(s1 - nm);
        float p2 = __expf(s2 - nm);
        l   = l * c + p1 + p2;
        o.x = o.x * c + p1 * v1.x + p2 * v2.x;
        o.y = o.y * c + p1 * v1.y + p2 * v2.y;
        o.z = o.z * c + p1 * v1.z + p2 * v2.z;
        o.w = o.w * c + p1 * v1.w + p2 * v2.w;
        m   = nm;
    }

    // new token (row 4096) handled by warp 0
    if (w == 0) {
        const float4* Kn = reinterpret_cast<const float4*>(g_kn + b * DIM + h * HD);
        const float4* Vn = reinterpret_cast<const float4*>(g_vn + b * DIM + h * HD);
        float4 kv = Kn[lane];
        float4 vv = Vn[lane];
        float s = q4.x * kv.x + q4.y * kv.y + q4.z * kv.z + q4.w * kv.w;
#pragma unroll
        for (int off = 16; off; off >>= 1)
            s += __shfl_xor_sync(0xffffffffu, s, off);
        s *= scale;
        float nm = fmaxf(m, s);
        float c  = __expf(m - nm);
        float p  = __expf(s - nm);
        l   = l * c + p;
        o.x = o.x * c + p * vv.x;
        o.y = o.y * c + p * vv.y;
        o.z = o.z * c + p * vv.z;
        o.w = o.w * c + p * vv.w;
        m   = nm;
    }

    // merge 8 warp-partials
    __shared__ float  sm[8];
    __shared__ float  sl[8];
    __shared__ float4 so[8][32];
    so[w][lane] = o;
    if (lane == 0) { sm[w] = m; sl[w] = l; }
    __syncthreads();

    if (tid < HD) {
        int d = tid;
        float gm = sm[0];
#pragma unroll
        for (int i = 1; i < 8; i++) gm = fmaxf(gm, sm[i]);
        const float* sof = reinterpret_cast<const float*>(so);
        float num = 0.f, den = 0.f;
#pragma unroll
        for (int i = 0; i < 8; i++) {
            float f = __expf(sm[i] - gm);
            num += f * sof[i * HD + d];
            den += f * sl[i];
        }
        // write transposed for oproj
        g_attT[(size_t)(h * HD + d) * BATCH + b] = num / den;
    }
}

// ---------------------------------------------------------------------------
extern "C" void kernel_launch(void* const* d_in, const int* in_sizes, int n_in,
                              void* d_out, int out_size) {
    const float* x  = (const float*)d_in[0];
    const float* kc = (const float*)d_in[1];
    const float* vc = (const float*)d_in[2];
    const float* wq = (const float*)d_in[3];
    const float* wk = (const float*)d_in[4];
    const float* wv = (const float*)d_in[5];
    const float* wo = (const float*)d_in[6];
    float* out = (float*)d_out;

    transpose_x<<<(BATCH * DIM) / 256, 256>>>(x);
    qkv_gemm  <<<3 * DIM / 32, 256>>>(wq, wk, wv);
    decode_attn<<<BATCH * NH, 256>>>(kc, vc);
    oproj_gemm<<<DIM / 32, 256>>>(wo, out);
}

// round 5
// speedup vs baseline: 1.5087x; 1.5087x over previous
#include <cuda_runtime.h>
#include <math.h>

#define DIM   4096
#define NH    32
#define HD    128
#define SEQ   4096
#define BATCH 16

typedef unsigned long long u64;

// Scratch (allocation-free)
__device__ float g_q  [BATCH * DIM];
__device__ float g_kn [BATCH * DIM];
__device__ float g_vn [BATCH * DIM];
__device__ float g_att[BATCH * DIM];

// ---------------- packed fp32x2 helpers ----------------
__device__ __forceinline__ u64 ffma2(u64 a, u64 b, u64 c) {
    u64 d; asm("fma.rn.f32x2 %0, %1, %2, %3;" : "=l"(d) : "l"(a), "l"(b), "l"(c)); return d;
}
__device__ __forceinline__ void unpack2(u64 v, float& lo, float& hi) {
    asm("mov.b64 {%0, %1}, %2;" : "=f"(lo), "=f"(hi) : "l"(v));
}

// ---------------------------------------------------------------------------
// Skinny GEMM: out[b][j] = dot(x[b,:], W[j,:]).  x stays in native [b][k]
// layout (L2-resident, coalesced). Each warp: 4 consecutive W rows x 8
// batches, K split over 32 lanes, k-pairs packed into f32x2 FFMAs.
// Warp pairs (w, w^1) share the same 4 rows, different batch half.
// NOTE: X2/W2 are ulonglong2* => 16 bytes = 4 floats per element,
//       so a DIM-float row is DIM/4 elements.
// ---------------------------------------------------------------------------
#define ROW_U2 (DIM / 4)   // ulonglong2 elements per 4096-float row

__device__ __forceinline__ void gemm_warp(const float* __restrict__ x,
                                          const float* __restrict__ Wrows, // W + j0*DIM
                                          float* __restrict__ out,
                                          int j0, int bh /* 0 or 8 */) {
    int lane = threadIdx.x & 31;

    u64 acc[4][8];
#pragma unroll
    for (int r = 0; r < 4; r++)
#pragma unroll
        for (int b = 0; b < 8; b++) acc[r][b] = 0ull;

    const ulonglong2* W2[4];
#pragma unroll
    for (int r = 0; r < 4; r++)
        W2[r] = reinterpret_cast<const ulonglong2*>(Wrows + (size_t)r * DIM);
    const ulonglong2* X2 = reinterpret_cast<const ulonglong2*>(x);

    for (int kb = 0; kb < DIM / 128; kb++) {
        int fidx = kb * 32 + lane;            // 16-byte chunk index (4 floats)

        ulonglong2 w[4];
#pragma unroll
        for (int r = 0; r < 4; r++) w[r] = __ldcs(W2[r] + fidx);

#pragma unroll
        for (int b = 0; b < 8; b++) {
            ulonglong2 xv = __ldg(X2 + (size_t)(bh + b) * ROW_U2 + fidx);
#pragma unroll
            for (int r = 0; r < 4; r++) {
                acc[r][b] = ffma2(w[r].x, xv.x, acc[r][b]);
                acc[r][b] = ffma2(w[r].y, xv.y, acc[r][b]);
            }
        }
    }

    // collapse k-pairs, then butterfly over lanes
    float s[4][8];
#pragma unroll
    for (int r = 0; r < 4; r++)
#pragma unroll
        for (int b = 0; b < 8; b++) {
            float lo, hi;
            unpack2(acc[r][b], lo, hi);
            float v = lo + hi;
#pragma unroll
            for (int off = 16; off; off >>= 1)
                v += __shfl_xor_sync(0xffffffffu, v, off);
            s[r][b] = v;
        }

    if (lane == 0) {
#pragma unroll
        for (int r = 0; r < 4; r++)
#pragma unroll
            for (int b = 0; b < 8; b++)
                out[(size_t)(bh + b) * DIM + j0 + r] = s[r][b];
    }
}

// QKV: 768 blocks x 256 threads. Block covers 16 consecutive fused rows
// (4 row-groups x 2 batch-half warps). Blocks never straddle a matrix.
__global__ void __launch_bounds__(256, 2) qkv_gemm(const float* __restrict__ x,
                                                   const float* __restrict__ wq,
                                                   const float* __restrict__ wk,
                                                   const float* __restrict__ wv) {
    int w  = threadIdx.x >> 5;
    int jg = blockIdx.x * 16 + (w >> 1) * 4;   // global fused row
    int bh = (w & 1) * 8;
    int which = jg >> 12;
    int jl    = jg & (DIM - 1);
    const float* W   = (which == 0) ? wq  : (which == 1) ? wk   : wv;
    float*       out = (which == 0) ? g_q : (which == 1) ? g_kn : g_vn;
    gemm_warp(x, W + (size_t)jl * DIM, out, jl, bh);
}

// O projection: 256 blocks x 256 threads, consumes g_att (native layout).
__global__ void __launch_bounds__(256, 2) oproj_gemm(const float* __restrict__ wo,
                                                     float* __restrict__ out) {
    int w  = threadIdx.x >> 5;
    int j  = blockIdx.x * 16 + (w >> 1) * 4;
    int bh = (w & 1) * 8;
    gemm_warp(g_att, wo + (size_t)j * DIM, out, j, bh);
}

// ---------------------------------------------------------------------------
// Decode attention. One block per (b,h): 512 blocks, 8 warps. Each warp
// processes row pairs (r, r+8) stepping 16 (2 independent shuffle chains
// interleaved). Streaming loads on K/V (no L2 reuse anyway).
// ---------------------------------------------------------------------------
__global__ void __launch_bounds__(256) decode_attn(const float* __restrict__ kc,
                                                   const float* __restrict__ vc) {
    int bh   = blockIdx.x;
    int b    = bh >> 5;
    int h    = bh & 31;
    int tid  = threadIdx.x;
    int w    = tid >> 5;
    int lane = tid & 31;

    const float4* K = reinterpret_cast<const float4*>(kc + (size_t)bh * SEQ * HD);
    const float4* V = reinterpret_cast<const float4*>(vc + (size_t)bh * SEQ * HD);

    float4 q4 = reinterpret_cast<const float4*>(g_q + b * DIM + h * HD)[lane];
    const float scale = 0.08838834764831845f;   // 1/sqrt(128)

    float  m = -INFINITY;
    float  l = 0.f;
    float4 o = make_float4(0.f, 0.f, 0.f, 0.f);

    for (int i = 0; i < SEQ / 16; i++) {
        int r1 = i * 16 + w;
        int r2 = r1 + 8;
        float4 k1 = __ldcs(K + (size_t)r1 * (HD / 4) + lane);
        float4 v1 = __ldcs(V + (size_t)r1 * (HD / 4) + lane);
        float4 k2 = __ldcs(K + (size_t)r2 * (HD / 4) + lane);
        float4 v2 = __ldcs(V + (size_t)r2 * (HD / 4) + lane);

        float s1 = q4.x * k1.x + q4.y * k1.y + q4.z * k1.z + q4.w * k1.w;
        float s2 = q4.x * k2.x + q4.y * k2.y + q4.z * k2.z + q4.w * k2.w;
#pragma unroll
        for (int off = 16; off; off >>= 1) {
            s1 += __shfl_xor_sync(0xffffffffu, s1, off);
            s2 += __shfl_xor_sync(0xffffffffu, s2, off);
        }
        s1 *= scale;
        s2 *= scale;

        float nm = fmaxf(m, fmaxf(s1, s2));
        float c  = __expf(m - nm);
        float p1 = __expf(s1 - nm);
        float p2 = __expf(s2 - nm);
        l   = l * c + p1 + p2;
        o.x = o.x * c + p1 * v1.x + p2 * v2.x;
        o.y = o.y * c + p1 * v1.y + p2 * v2.y;
        o.z = o.z * c + p1 * v1.z + p2 * v2.z;
        o.w = o.w * c + p1 * v1.w + p2 * v2.w;
        m   = nm;
    }

    // new token (row 4096) handled by warp 0
    if (w == 0) {
        const float4* Kn = reinterpret_cast<const float4*>(g_kn + b * DIM + h * HD);
        const float4* Vn = reinterpret_cast<const float4*>(g_vn + b * DIM + h * HD);
        float4 kv = Kn[lane];
        float4 vv = Vn[lane];
        float s = q4.x * kv.x + q4.y * kv.y + q4.z * kv.z + q4.w * kv.w;
#pragma unroll
        for (int off = 16; off; off >>= 1)
            s += __shfl_xor_sync(0xffffffffu, s, off);
        s *= scale;
        float nm = fmaxf(m, s);
        float c  = __expf(m - nm);
        float p  = __expf(s - nm);
        l   = l * c + p;
        o.x = o.x * c + p * vv.x;
        o.y = o.y * c + p * vv.y;
        o.z = o.z * c + p * vv.z;
        o.w = o.w * c + p * vv.w;
        m   = nm;
    }

    // merge 8 warp-partials
    __shared__ float  sm[8];
    __shared__ float  sl[8];
    __shared__ float4 so[8][32];
    so[w][lane] = o;
    if (lane == 0) { sm[w] = m; sl[w] = l; }
    __syncthreads();

    if (tid < HD) {
        int d = tid;
        float gm = sm[0];
#pragma unroll
        for (int i = 1; i < 8; i++) gm = fmaxf(gm, sm[i]);
        const float* sof = reinterpret_cast<const float*>(so);
        float num = 0.f, den = 0.f;
#pragma unroll
        for (int i = 0; i < 8; i++) {
            float f = __expf(sm[i] - gm);
            num += f * sof[i * HD + d];
            den += f * sl[i];
        }
        g_att[b * DIM + h * HD + d] = num / den;
    }
}

// ---------------------------------------------------------------------------
extern "C" void kernel_launch(void* const* d_in, const int* in_sizes, int n_in,
                              void* d_out, int out_size) {
    const float* x  = (const float*)d_in[0];
    const float* kc = (const float*)d_in[1];
    const float* vc = (const float*)d_in[2];
    const float* wq = (const float*)d_in[3];
    const float* wk = (const float*)d_in[4];
    const float* wv = (const float*)d_in[5];
    const float* wo = (const float*)d_in[6];
    float* out = (float*)d_out;

    qkv_gemm  <<<3 * DIM / 16, 256>>>(x, wq, wk, wv);
    decode_attn<<<BATCH * NH, 256>>>(kc, vc);
    oproj_gemm<<<DIM / 16, 256>>>(wo, out);
}

// round 6
// speedup vs baseline: 1.5300x; 1.0141x over previous
#include <cuda_runtime.h>
#include <math.h>

#define DIM   4096
#define NH    32
#define HD    128
#define SEQ   4096
#define BATCH 16

typedef unsigned long long u64;

// Scratch (allocation-free)
__device__ float g_q  [BATCH * DIM];
__device__ float g_kn [BATCH * DIM];
__device__ float g_vn [BATCH * DIM];
__device__ float g_att[BATCH * DIM];

// ---------------- packed fp32x2 helpers ----------------
__device__ __forceinline__ u64 ffma2(u64 a, u64 b, u64 c) {
    u64 d; asm("fma.rn.f32x2 %0, %1, %2, %3;" : "=l"(d) : "l"(a), "l"(b), "l"(c)); return d;
}
__device__ __forceinline__ void unpack2(u64 v, float& lo, float& hi) {
    asm("mov.b64 {%0, %1}, %2;" : "=f"(lo), "=f"(hi) : "l"(v));
}

#define ROW_U2 (DIM / 4)   // ulonglong2 (16B) elements per 4096-float row

// ---------------------------------------------------------------------------
// Skinny GEMM: out[b][j] = dot(x[b,:], W[j,:]).  Warp tile: 4 W rows x 8
// batches, K split over lanes, k-pairs packed in f32x2.
// Loads are explicitly two-phase per k-chunk so ptxas front-batches them
// (MLP ~8 LDG.128 in flight per warp) instead of serializing on each xv.
// ---------------------------------------------------------------------------
__device__ __forceinline__ void gemm_warp(const float* __restrict__ x,
                                          const float* __restrict__ Wrows,
                                          float* __restrict__ out,
                                          int j0, int bh /* 0 or 8 */) {
    int lane = threadIdx.x & 31;

    u64 acc[4][8];
#pragma unroll
    for (int r = 0; r < 4; r++)
#pragma unroll
        for (int b = 0; b < 8; b++) acc[r][b] = 0ull;

    const ulonglong2* W2 = reinterpret_cast<const ulonglong2*>(Wrows);
    const ulonglong2* X2 = reinterpret_cast<const ulonglong2*>(x) + (size_t)bh * ROW_U2;

#pragma unroll 1
    for (int kb = 0; kb < DIM / 128; kb++) {
        int fidx = kb * 32 + lane;            // 16-byte chunk index (4 k's)

        // ---- phase A: W rows + first 4 batches (8 loads in flight) ----
        ulonglong2 w0 = __ldcs(W2 + 0 * ROW_U2 + fidx);
        ulonglong2 w1 = __ldcs(W2 + 1 * ROW_U2 + fidx);
        ulonglong2 w2 = __ldcs(W2 + 2 * ROW_U2 + fidx);
        ulonglong2 w3 = __ldcs(W2 + 3 * ROW_U2 + fidx);
        ulonglong2 x0 = X2[0 * ROW_U2 + fidx];
        ulonglong2 x1 = X2[1 * ROW_U2 + fidx];
        ulonglong2 x2 = X2[2 * ROW_U2 + fidx];
        ulonglong2 x3 = X2[3 * ROW_U2 + fidx];

#pragma unroll
        for (int b = 0; b < 4; b++) {
            ulonglong2 xv = (b == 0) ? x0 : (b == 1) ? x1 : (b == 2) ? x2 : x3;
            acc[0][b] = ffma2(w0.x, xv.x, acc[0][b]);
            acc[0][b] = ffma2(w0.y, xv.y, acc[0][b]);
            acc[1][b] = ffma2(w1.x, xv.x, acc[1][b]);
            acc[1][b] = ffma2(w1.y, xv.y, acc[1][b]);
            acc[2][b] = ffma2(w2.x, xv.x, acc[2][b]);
            acc[2][b] = ffma2(w2.y, xv.y, acc[2][b]);
            acc[3][b] = ffma2(w3.x, xv.x, acc[3][b]);
            acc[3][b] = ffma2(w3.y, xv.y, acc[3][b]);
        }

        // ---- phase B: last 4 batches ----
        ulonglong2 x4 = X2[4 * ROW_U2 + fidx];
        ulonglong2 x5 = X2[5 * ROW_U2 + fidx];
        ulonglong2 x6 = X2[6 * ROW_U2 + fidx];
        ulonglong2 x7 = X2[7 * ROW_U2 + fidx];

#pragma unroll
        for (int b = 4; b < 8; b++) {
            ulonglong2 xv = (b == 4) ? x4 : (b == 5) ? x5 : (b == 6) ? x6 : x7;
            acc[0][b] = ffma2(w0.x, xv.x, acc[0][b]);
            acc[0][b] = ffma2(w0.y, xv.y, acc[0][b]);
            acc[1][b] = ffma2(w1.x, xv.x, acc[1][b]);
            acc[1][b] = ffma2(w1.y, xv.y, acc[1][b]);
            acc[2][b] = ffma2(w2.x, xv.x, acc[2][b]);
            acc[2][b] = ffma2(w2.y, xv.y, acc[2][b]);
            acc[3][b] = ffma2(w3.x, xv.x, acc[3][b]);
            acc[3][b] = ffma2(w3.y, xv.y, acc[3][b]);
        }
    }

    // collapse k-pairs, then butterfly over lanes
#pragma unroll
    for (int r = 0; r < 4; r++)
#pragma unroll
        for (int b = 0; b < 8; b++) {
            float lo, hi;
            unpack2(acc[r][b], lo, hi);
            float v = lo + hi;
#pragma unroll
            for (int off = 16; off; off >>= 1)
                v += __shfl_xor_sync(0xffffffffu, v, off);
            if (lane == 0)
                out[(size_t)(bh + b) * DIM + j0 + r] = v;
        }
}

// QKV: 768 blocks x 256 threads. Block = 16 consecutive fused rows
// (4 row-groups x 2 batch-half warps). Blocks never straddle a matrix.
__global__ void __launch_bounds__(256, 2) qkv_gemm(const float* __restrict__ x,
                                                   const float* __restrict__ wq,
                                                   const float* __restrict__ wk,
                                                   const float* __restrict__ wv) {
    int w  = threadIdx.x >> 5;
    int jg = blockIdx.x * 16 + (w >> 1) * 4;
    int bh = (w & 1) * 8;
    int which = jg >> 12;
    int jl    = jg & (DIM - 1);
    const float* W   = (which == 0) ? wq  : (which == 1) ? wk   : wv;
    float*       out = (which == 0) ? g_q : (which == 1) ? g_kn : g_vn;
    gemm_warp(x, W + (size_t)jl * DIM, out, jl, bh);
}

// O projection: 256 blocks x 256 threads, consumes g_att (native layout).
__global__ void __launch_bounds__(256, 2) oproj_gemm(const float* __restrict__ wo,
                                                     float* __restrict__ out) {
    int w  = threadIdx.x >> 5;
    int j  = blockIdx.x * 16 + (w >> 1) * 4;
    int bh = (w & 1) * 8;
    gemm_warp(g_att, wo + (size_t)j * DIM, out, j, bh);
}

// ---------------------------------------------------------------------------
// Decode attention (unchanged from round 5 — ~80% of HBM already).
// One block per (b,h): 512 blocks, 8 warps, 2-row unroll, streaming loads.
// ---------------------------------------------------------------------------
__global__ void __launch_bounds__(256) decode_attn(const float* __restrict__ kc,
                                                   const float* __restrict__ vc) {
    int bh   = blockIdx.x;
    int b    = bh >> 5;
    int h    = bh & 31;
    int tid  = threadIdx.x;
    int w    = tid >> 5;
    int lane = tid & 31;

    const float4* K = reinterpret_cast<const float4*>(kc + (size_t)bh * SEQ * HD);
    const float4* V = reinterpret_cast<const float4*>(vc + (size_t)bh * SEQ * HD);

    float4 q4 = reinterpret_cast<const float4*>(g_q + b * DIM + h * HD)[lane];
    const float scale = 0.08838834764831845f;   // 1/sqrt(128)

    float  m = -INFINITY;
    float  l = 0.f;
    float4 o = make_float4(0.f, 0.f, 0.f, 0.f);

    for (int i = 0; i < SEQ / 16; i++) {
        int r1 = i * 16 + w;
        int r2 = r1 + 8;
        float4 k1 = __ldcs(K + (size_t)r1 * (HD / 4) + lane);
        float4 v1 = __ldcs(V + (size_t)r1 * (HD / 4) + lane);
        float4 k2 = __ldcs(K + (size_t)r2 * (HD / 4) + lane);
        float4 v2 = __ldcs(V + (size_t)r2 * (HD / 4) + lane);

        float s1 = q4.x * k1.x + q4.y * k1.y + q4.z * k1.z + q4.w * k1.w;
        float s2 = q4.x * k2.x + q4.y * k2.y + q4.z * k2.z + q4.w * k2.w;
#pragma unroll
        for (int off = 16; off; off >>= 1) {
            s1 += __shfl_xor_sync(0xffffffffu, s1, off);
            s2 += __shfl_xor_sync(0xffffffffu, s2, off);
        }
        s1 *= scale;
        s2 *= scale;

        float nm = fmaxf(m, fmaxf(s1, s2));
        float c  = __expf(m - nm);
        float p1 = __expf(s1 - nm);
        float p2 = __expf(s2 - nm);
        l   = l * c + p1 + p2;
        o.x = o.x * c + p1 * v1.x + p2 * v2.x;
        o.y = o.y * c + p1 * v1.y + p2 * v2.y;
        o.z = o.z * c + p1 * v1.z + p2 * v2.z;
        o.w = o.w * c + p1 * v1.w + p2 * v2.w;
        m   = nm;
    }

    // new token (row 4096) handled by warp 0
    if (w == 0) {
        const float4* Kn = reinterpret_cast<const float4*>(g_kn + b * DIM + h * HD);
        const float4* Vn = reinterpret_cast<const float4*>(g_vn + b * DIM + h * HD);
        float4 kv = Kn[lane];
        float4 vv = Vn[lane];
        float s = q4.x * kv.x + q4.y * kv.y + q4.z * kv.z + q4.w * kv.w;
#pragma unroll
        for (int off = 16; off; off >>= 1)
            s += __shfl_xor_sync(0xffffffffu, s, off);
        s *= scale;
        float nm = fmaxf(m, s);
        float c  = __expf(m - nm);
        float p  = __expf(s - nm);
        l   = l * c + p;
        o.x = o.x * c + p * vv.x;
        o.y = o.y * c + p * vv.y;
        o.z = o.z * c + p * vv.z;
        o.w = o.w * c + p * vv.w;
        m   = nm;
    }

    // merge 8 warp-partials
    __shared__ float  sm[8];
    __shared__ float  sl[8];
    __shared__ float4 so[8][32];
    so[w][lane] = o;
    if (lane == 0) { sm[w] = m; sl[w] = l; }
    __syncthreads();

    if (tid < HD) {
        int d = tid;
        float gm = sm[0];
#pragma unroll
        for (int i = 1; i < 8; i++) gm = fmaxf(gm, sm[i]);
        const float* sof = reinterpret_cast<const float*>(so);
        float num = 0.f, den = 0.f;
#pragma unroll
        for (int i = 0; i < 8; i++) {
            float f = __expf(sm[i] - gm);
            num += f * sof[i * HD + d];
            den += f * sl[i];
        }
        g_att[b * DIM + h * HD + d] = num / den;
    }
}

// ---------------------------------------------------------------------------
extern "C" void kernel_launch(void* const* d_in, const int* in_sizes, int n_in,
                              void* d_out, int out_size) {
    const float* x  = (const float*)d_in[0];
    const float* kc = (const float*)d_in[1];
    const float* vc = (const float*)d_in[2];
    const float* wq = (const float*)d_in[3];
    const float* wk = (const float*)d_in[4];
    const float* wv = (const float*)d_in[5];
    const float* wo = (const float*)d_in[6];
    float* out = (float*)d_out;

    qkv_gemm  <<<3 * DIM / 16, 256>>>(x, wq, wk, wv);
    decode_attn<<<BATCH * NH, 256>>>(kc, vc);
    oproj_gemm<<<DIM / 16, 256>>>(wo, out);
}